// round 2
// baseline (speedup 1.0000x reference)
#include <cuda_runtime.h>
#include <cstdint>

#define Bsz 2
#define S   2048
#define D   1024
#define H   16
#define HD  64
#define EPSV 1e-8f

// Scratch (alloc-free rule: __device__ globals)
__device__ float g_qk[(size_t)Bsz * S * 2 * D];   // [4096][2048]: cols 0..1023 = Q, 1024..2047 = K
__device__ float g_attn[(size_t)Bsz * S * D];     // [4096][1024]

// ---------------------------------------------------------------------------
// C[M][N] = A[M][K] * Bw[N][K]^T + bias[N]
// 64x64 tile, BK=32, 256 threads, 4x4 register frags per thread.
// ---------------------------------------------------------------------------
__global__ __launch_bounds__(256)
void gemm_nt(const float* __restrict__ A, const float* __restrict__ Bw,
             const float* __restrict__ bias, float* __restrict__ C,
             int K, int N) {
    __shared__ float As[64][36];   // [row][kk], padded
    __shared__ float Bs[32][68];   // [kk][col], transposed, padded (16B-aligned rows)

    const int tid = threadIdx.x;
    const int tx = tid & 15, ty = tid >> 4;
    const int row0 = blockIdx.y * 64, col0 = blockIdx.x * 64;

    float acc[4][4] = {};

    for (int kt = 0; kt < K; kt += 32) {
        // A tile: 64 rows x 32 cols, natural layout
        #pragma unroll
        for (int l = tid; l < 64 * 8; l += 256) {
            int r = l >> 3, c4 = l & 7;
            float4 v = *(const float4*)(A + (size_t)(row0 + r) * K + kt + c4 * 4);
            *(float4*)&As[r][c4 * 4] = v;
        }
        // B tile: 64 rows x 32 cols, transposed into Bs[kk][col]
        #pragma unroll
        for (int l = tid; l < 64 * 8; l += 256) {
            int r = l >> 3, c4 = l & 7;
            float4 v = *(const float4*)(Bw + (size_t)(col0 + r) * K + kt + c4 * 4);
            Bs[c4 * 4 + 0][r] = v.x;
            Bs[c4 * 4 + 1][r] = v.y;
            Bs[c4 * 4 + 2][r] = v.z;
            Bs[c4 * 4 + 3][r] = v.w;
        }
        __syncthreads();

        #pragma unroll
        for (int kk = 0; kk < 32; kk++) {
            float a0 = As[ty * 4 + 0][kk];
            float a1 = As[ty * 4 + 1][kk];
            float a2 = As[ty * 4 + 2][kk];
            float a3 = As[ty * 4 + 3][kk];
            float4 b4 = *(float4*)&Bs[kk][tx * 4];
            acc[0][0] += a0 * b4.x; acc[0][1] += a0 * b4.y; acc[0][2] += a0 * b4.z; acc[0][3] += a0 * b4.w;
            acc[1][0] += a1 * b4.x; acc[1][1] += a1 * b4.y; acc[1][2] += a1 * b4.z; acc[1][3] += a1 * b4.w;
            acc[2][0] += a2 * b4.x; acc[2][1] += a2 * b4.y; acc[2][2] += a2 * b4.z; acc[2][3] += a2 * b4.w;
            acc[3][0] += a3 * b4.x; acc[3][1] += a3 * b4.y; acc[3][2] += a3 * b4.z; acc[3][3] += a3 * b4.w;
        }
        __syncthreads();
    }

    float4 bb = *(const float4*)(bias + col0 + tx * 4);
    #pragma unroll
    for (int i = 0; i < 4; i++) {
        float4 o;
        o.x = acc[i][0] + bb.x;
        o.y = acc[i][1] + bb.y;
        o.z = acc[i][2] + bb.z;
        o.w = acc[i][3] + bb.w;
        *(float4*)(C + (size_t)(row0 + ty * 4 + i) * N + col0 + tx * 4) = o;
    }
}

// ---------------------------------------------------------------------------
// Attention: per (b, h, 64-query tile). Stream keys in 32-wide tiles.
// Single pass (no running max; scores are O(1) magnitude, fp32 safe):
//   Z  += sum_j exp(s)
//   Zm += sum_j exp(s)*M
//   O  += sum_j exp(s)*M*V_j
// out = O / (Zm + EPS*Z)   ==  (A*M / (sum|A*M| + EPS)) @ V
// ---------------------------------------------------------------------------
__global__ __launch_bounds__(256)
void attn_kernel(const float* __restrict__ Vin, const float* __restrict__ Min) {
    __shared__ float Qs[64][68];   // [q][d], pre-scaled by 1/sqrt(HD)
    __shared__ float Ks[32][68];   // [k][d]
    __shared__ float Vs[32][68];   // [k][d]
    __shared__ float As[64][36];   // [q][k] = exp(s)*M

    const int tid = threadIdx.x;
    const int tx = tid & 15, ty = tid >> 4;
    const int b = blockIdx.z, h = blockIdx.y;
    const int q0 = blockIdx.x * 64;
    const float scale = 0.125f;  // 1/sqrt(64)

    // Load Q tile (pre-scaled)
    const float* Qg = g_qk + ((size_t)(b * S + q0)) * (2 * D) + h * HD;
    #pragma unroll
    for (int l = tid; l < 64 * 16; l += 256) {
        int r = l >> 4, c4 = l & 15;
        float4 v = *(const float4*)(Qg + (size_t)r * (2 * D) + c4 * 4);
        v.x *= scale; v.y *= scale; v.z *= scale; v.w *= scale;
        *(float4*)&Qs[r][c4 * 4] = v;
    }

    float O[4][4] = {};
    float Z[4] = {}, Zm[4] = {};

    for (int k0 = 0; k0 < S; k0 += 32) {
        const float* Kg = g_qk + ((size_t)(b * S + k0)) * (2 * D) + D + h * HD;
        const float* Vg = Vin + (((size_t)(b * S + k0)) * H + h) * HD;
        #pragma unroll
        for (int l = tid; l < 32 * 16; l += 256) {
            int r = l >> 4, c4 = l & 15;
            *(float4*)&Ks[r][c4 * 4] = *(const float4*)(Kg + (size_t)r * (2 * D) + c4 * 4);
            *(float4*)&Vs[r][c4 * 4] = *(const float4*)(Vg + (size_t)r * (H * HD) + c4 * 4);
        }
        __syncthreads();

        // Scores: rows ty*4+i, cols tx*2+j
        float s[4][2] = {};
        #pragma unroll
        for (int d4 = 0; d4 < 16; d4++) {
            float4 kA = *(float4*)&Ks[tx * 2 + 0][d4 * 4];
            float4 kB = *(float4*)&Ks[tx * 2 + 1][d4 * 4];
            #pragma unroll
            for (int i = 0; i < 4; i++) {
                float4 q = *(float4*)&Qs[ty * 4 + i][d4 * 4];
                s[i][0] += q.x * kA.x + q.y * kA.y + q.z * kA.z + q.w * kA.w;
                s[i][1] += q.x * kB.x + q.y * kB.y + q.z * kB.z + q.w * kB.w;
            }
        }

        // exp, mask, accumulate row sums, stage exp*M into As
        #pragma unroll
        for (int i = 0; i < 4; i++) {
            float e0 = __expf(s[i][0]);
            float e1 = __expf(s[i][1]);
            float2 m = *(const float2*)(Min + ((size_t)b * S + q0 + ty * 4 + i) * S + k0 + tx * 2);
            Z[i] += e0 + e1;
            float em0 = e0 * m.x, em1 = e1 * m.y;
            Zm[i] += em0 + em1;
            As[ty * 4 + i][tx * 2 + 0] = em0;
            As[ty * 4 + i][tx * 2 + 1] = em1;
        }
        __syncthreads();

        // O += As[64x32] @ Vs[32x64]
        #pragma unroll
        for (int j = 0; j < 32; j++) {
            float4 v4 = *(float4*)&Vs[j][tx * 4];
            #pragma unroll
            for (int i = 0; i < 4; i++) {
                float a = As[ty * 4 + i][j];
                O[i][0] += a * v4.x;
                O[i][1] += a * v4.y;
                O[i][2] += a * v4.z;
                O[i][3] += a * v4.w;
            }
        }
        __syncthreads();
    }

    // Reduce Z, Zm across the 16-lane tx group (xor stays in-group), write out
    #pragma unroll
    for (int i = 0; i < 4; i++) {
        float z = Z[i], zm = Zm[i];
        #pragma unroll
        for (int off = 1; off < 16; off <<= 1) {
            z  += __shfl_xor_sync(0xffffffffu, z, off);
            zm += __shfl_xor_sync(0xffffffffu, zm, off);
        }
        float inv = 1.0f / (zm + EPSV * z);
        float4 o;
        o.x = O[i][0] * inv; o.y = O[i][1] * inv;
        o.z = O[i][2] * inv; o.w = O[i][3] * inv;
        *(float4*)(g_attn + ((size_t)(b * S + q0 + ty * 4 + i)) * D + h * HD + tx * 4) = o;
    }
}

// ---------------------------------------------------------------------------
extern "C" void kernel_launch(void* const* d_in, const int* in_sizes, int n_in,
                              void* d_out, int out_size) {
    const float* x        = (const float*)d_in[0];  // [B,S,D]
    const float* Vin      = (const float*)d_in[1];  // [B,S,H,HD]
    const float* Min      = (const float*)d_in[2];  // [B,S,S]
    const float* in_proj_w= (const float*)d_in[3];  // [3D,D] (rows 0..2D-1 used)
    const float* in_proj_b= (const float*)d_in[4];  // [3D]
    const float* out_w    = (const float*)d_in[5];  // [D,D]
    const float* out_b    = (const float*)d_in[6];  // [D]
    float* out            = (float*)d_out;          // [B,S,D]

    float* qk = nullptr;
    float* at = nullptr;
    cudaGetSymbolAddress((void**)&qk, g_qk);
    cudaGetSymbolAddress((void**)&at, g_attn);

    const int M = Bsz * S;  // 4096

    // Stage 1: QK = x @ in_proj_w[0:2D]^T + b[0:2D]   -> [4096][2048]
    gemm_nt<<<dim3((2 * D) / 64, M / 64), 256>>>(x, in_proj_w, in_proj_b, qk, D, 2 * D);

    // Stage 2: masked-renormalized attention -> g_attn [4096][1024]
    attn_kernel<<<dim3(S / 64, H, Bsz), 256>>>(Vin, Min);

    // Stage 3: out = attn @ out_w^T + out_b
    gemm_nt<<<dim3(D / 64, M / 64), 256>>>(at, out_w, out_b, out, D, D);
}

// round 3
// speedup vs baseline: 1.2941x; 1.2941x over previous
#include <cuda_runtime.h>
#include <cstdint>

#define Bsz 2
#define S   2048
#define D   1024
#define H   16
#define HD  64
#define EPSV 1e-8f

// Scratch (alloc-free rule: __device__ globals)
__device__ float g_qk[(size_t)Bsz * S * 2 * D];   // [4096][2048]: cols 0..1023 = Q, 1024..2047 = K
__device__ float g_attn[(size_t)Bsz * S * D];     // [4096][1024]

// ---------------------------------------------------------------------------
// C[M][N] = A[M][K] * Bw[N][K]^T + bias[N]
// 128x128 tile, BK=16, 256 threads, 8x8 register frags (4+4 split).
// Smem staged k-major so frag loads are conflict-free LDS.128.
// ---------------------------------------------------------------------------
__global__ __launch_bounds__(256, 2)
void gemm_nt(const float* __restrict__ A, const float* __restrict__ Bw,
             const float* __restrict__ bias, float* __restrict__ C,
             int K, int N) {
    __shared__ float As[16][132];   // [k][m]
    __shared__ float Bs[16][132];   // [k][n]

    const int tid = threadIdx.x;
    const int tx = tid & 15, ty = tid >> 4;
    const int tx4 = tx * 4, ty4 = ty * 4;
    const int row0 = blockIdx.y * 128, col0 = blockIdx.x * 128;

    float acc[8][8] = {};

    for (int kt = 0; kt < K; kt += 16) {
        // 128 rows x 16 k = 512 float4 per operand; 2 per thread
        #pragma unroll
        for (int i = 0; i < 2; i++) {
            int idx = tid + i * 256;
            int r = idx >> 2, c4 = idx & 3;
            float4 v = *(const float4*)(A + (size_t)(row0 + r) * K + kt + c4 * 4);
            As[c4 * 4 + 0][r] = v.x; As[c4 * 4 + 1][r] = v.y;
            As[c4 * 4 + 2][r] = v.z; As[c4 * 4 + 3][r] = v.w;
            float4 w = *(const float4*)(Bw + (size_t)(col0 + r) * K + kt + c4 * 4);
            Bs[c4 * 4 + 0][r] = w.x; Bs[c4 * 4 + 1][r] = w.y;
            Bs[c4 * 4 + 2][r] = w.z; Bs[c4 * 4 + 3][r] = w.w;
        }
        __syncthreads();

        #pragma unroll
        for (int kk = 0; kk < 16; kk++) {
            float af[8], bf[8];
            *(float4*)&af[0] = *(float4*)&As[kk][ty4];
            *(float4*)&af[4] = *(float4*)&As[kk][64 + ty4];
            *(float4*)&bf[0] = *(float4*)&Bs[kk][tx4];
            *(float4*)&bf[4] = *(float4*)&Bs[kk][64 + tx4];
            #pragma unroll
            for (int i = 0; i < 8; i++)
                #pragma unroll
                for (int j = 0; j < 8; j++)
                    acc[i][j] += af[i] * bf[j];
        }
        __syncthreads();
    }

    float4 bb0 = *(const float4*)(bias + col0 + tx4);
    float4 bb1 = *(const float4*)(bias + col0 + 64 + tx4);
    #pragma unroll
    for (int i = 0; i < 8; i++) {
        int r = row0 + ((i < 4) ? (ty4 + i) : (64 + ty4 + i - 4));
        float4 o0 = { acc[i][0] + bb0.x, acc[i][1] + bb0.y,
                      acc[i][2] + bb0.z, acc[i][3] + bb0.w };
        *(float4*)(C + (size_t)r * N + col0 + tx4) = o0;
        float4 o1 = { acc[i][4] + bb1.x, acc[i][5] + bb1.y,
                      acc[i][6] + bb1.z, acc[i][7] + bb1.w };
        *(float4*)(C + (size_t)r * N + col0 + 64 + tx4) = o1;
    }
}

// ---------------------------------------------------------------------------
// Attention: per (b, h, 128-query tile), keys streamed in 64-wide tiles.
// Single pass: Z += sum exp(s); Zm += sum exp(s)*M; O += sum exp(s)*M*V
// out = O / (Zm + EPS*Z)
// Smem (dynamic, 100KB): Qt[d][q] (d-major), Kt[d][k], Vs[k][d], Ps[k][q].
// ---------------------------------------------------------------------------
#define QT(d,q) sm[(d) * 132 + (q)]
#define KT(d,k) sm[8448 + (d) * 68 + (k)]
#define VS(k,d) sm[12800 + (k) * 68 + (d)]
#define PS(k,q) sm[17152 + (k) * 132 + (q)]
#define ATTN_SMEM (25600 * 4)

__global__ __launch_bounds__(256, 2)
void attn_kernel(const float* __restrict__ Vin, const float* __restrict__ Min) {
    extern __shared__ float sm[];

    const int tid = threadIdx.x;
    const int tx = tid & 15, ty = tid >> 4;
    const int tx4 = tx * 4, ty4 = ty * 4;
    const int b = blockIdx.z, h = blockIdx.y;
    const int q0 = blockIdx.x * 128;
    const float scale = 0.125f;  // 1/sqrt(64)

    // Q tile -> Qt[d][q], pre-scaled. 128 rows x 16 float4 = 2048 float4.
    const float* Qg = g_qk + ((size_t)(b * S + q0)) * (2 * D) + h * HD;
    #pragma unroll
    for (int i = 0; i < 8; i++) {
        int gi = tid + i * 256;
        int r = gi >> 4, c4 = gi & 15;
        float4 v = *(const float4*)(Qg + (size_t)r * (2 * D) + c4 * 4);
        QT(c4 * 4 + 0, r) = v.x * scale;
        QT(c4 * 4 + 1, r) = v.y * scale;
        QT(c4 * 4 + 2, r) = v.z * scale;
        QT(c4 * 4 + 3, r) = v.w * scale;
    }

    float O[8][4] = {};
    float Z[8] = {}, Zm[8] = {};

    for (int k0 = 0; k0 < S; k0 += 64) {
        __syncthreads();   // prev AV done before overwriting Kt/Vs (also covers Q load)

        // K tile -> Kt[d][k]; V tile -> Vs[k][d]. 64 rows x 16 float4 each.
        const float* Kg = g_qk + ((size_t)(b * S + k0)) * (2 * D) + D + h * HD;
        const float* Vg = Vin + (((size_t)(b * S + k0)) * H + h) * HD;
        #pragma unroll
        for (int i = 0; i < 4; i++) {
            int gi = tid + i * 256;
            int r = gi >> 4, c4 = gi & 15;
            float4 kv = *(const float4*)(Kg + (size_t)r * (2 * D) + c4 * 4);
            KT(c4 * 4 + 0, r) = kv.x;
            KT(c4 * 4 + 1, r) = kv.y;
            KT(c4 * 4 + 2, r) = kv.z;
            KT(c4 * 4 + 3, r) = kv.w;
            *(float4*)&VS(r, c4 * 4) = *(const float4*)(Vg + (size_t)r * (H * HD) + c4 * 4);
        }
        __syncthreads();

        // Scores: 8 q-rows x 4 k-cols per thread
        float s[8][4] = {};
        #pragma unroll 16
        for (int d = 0; d < 64; d++) {
            float qv[8], kv[4];
            *(float4*)&qv[0] = *(float4*)&QT(d, ty4);
            *(float4*)&qv[4] = *(float4*)&QT(d, 64 + ty4);
            *(float4*)&kv[0] = *(float4*)&KT(d, tx4);
            #pragma unroll
            for (int i = 0; i < 8; i++)
                #pragma unroll
                for (int j = 0; j < 4; j++)
                    s[i][j] += qv[i] * kv[j];
        }

        // exp, mask, row-sum accumulation, stage exp*M into Ps[k][q]
        #pragma unroll
        for (int i = 0; i < 8; i++) {
            int qi = (i < 4) ? (ty4 + i) : (64 + ty4 + i - 4);
            float4 m = *(const float4*)(Min + ((size_t)b * S + q0 + qi) * S + k0 + tx4);
            float e0 = __expf(s[i][0]);
            float e1 = __expf(s[i][1]);
            float e2 = __expf(s[i][2]);
            float e3 = __expf(s[i][3]);
            Z[i] += (e0 + e1) + (e2 + e3);
            float em0 = e0 * m.x, em1 = e1 * m.y, em2 = e2 * m.z, em3 = e3 * m.w;
            Zm[i] += (em0 + em1) + (em2 + em3);
            PS(tx4 + 0, qi) = em0;
            PS(tx4 + 1, qi) = em1;
            PS(tx4 + 2, qi) = em2;
            PS(tx4 + 3, qi) = em3;
        }
        __syncthreads();

        // O += Ps[64x128]^T-slice @ Vs[64x64]
        #pragma unroll 16
        for (int j = 0; j < 64; j++) {
            float pv[8], vv[4];
            *(float4*)&pv[0] = *(float4*)&PS(j, ty4);
            *(float4*)&pv[4] = *(float4*)&PS(j, 64 + ty4);
            *(float4*)&vv[0] = *(float4*)&VS(j, tx4);
            #pragma unroll
            for (int i = 0; i < 8; i++)
                #pragma unroll
                for (int c = 0; c < 4; c++)
                    O[i][c] += pv[i] * vv[c];
        }
    }

    // Reduce Z, Zm across the 16-lane tx group; normalize; write
    #pragma unroll
    for (int i = 0; i < 8; i++) {
        float z = Z[i], zm = Zm[i];
        #pragma unroll
        for (int off = 1; off < 16; off <<= 1) {
            z  += __shfl_xor_sync(0xffffffffu, z, off);
            zm += __shfl_xor_sync(0xffffffffu, zm, off);
        }
        float inv = 1.0f / (zm + EPSV * z);
        int qi = (i < 4) ? (ty4 + i) : (64 + ty4 + i - 4);
        float4 o = { O[i][0] * inv, O[i][1] * inv, O[i][2] * inv, O[i][3] * inv };
        *(float4*)(g_attn + ((size_t)(b * S + q0 + qi)) * D + h * HD + tx4) = o;
    }
}

// ---------------------------------------------------------------------------
extern "C" void kernel_launch(void* const* d_in, const int* in_sizes, int n_in,
                              void* d_out, int out_size) {
    const float* x         = (const float*)d_in[0];  // [B,S,D]
    const float* Vin       = (const float*)d_in[1];  // [B,S,H,HD]
    const float* Min       = (const float*)d_in[2];  // [B,S,S]
    const float* in_proj_w = (const float*)d_in[3];  // [3D,D] (rows 0..2D-1 used)
    const float* in_proj_b = (const float*)d_in[4];  // [3D]
    const float* out_w     = (const float*)d_in[5];  // [D,D]
    const float* out_b     = (const float*)d_in[6];  // [D]
    float* out             = (float*)d_out;          // [B,S,D]

    float* qk = nullptr;
    float* at = nullptr;
    cudaGetSymbolAddress((void**)&qk, g_qk);
    cudaGetSymbolAddress((void**)&at, g_attn);

    cudaFuncSetAttribute(attn_kernel, cudaFuncAttributeMaxDynamicSharedMemorySize, ATTN_SMEM);

    const int M = Bsz * S;  // 4096

    // Stage 1: QK = x @ in_proj_w[0:2D]^T + b[0:2D]   -> [4096][2048]
    gemm_nt<<<dim3((2 * D) / 128, M / 128), 256>>>(x, in_proj_w, in_proj_b, qk, D, 2 * D);

    // Stage 2: masked-renormalized attention -> g_attn [4096][1024]
    attn_kernel<<<dim3(S / 128, H, Bsz), 256, ATTN_SMEM>>>(Vin, Min);

    // Stage 3: out = attn @ out_w^T + out_b
    gemm_nt<<<dim3(D / 128, M / 128), 256>>>(at, out_w, out_b, out, D, D);
}

// round 6
// speedup vs baseline: 2.4917x; 1.9255x over previous
#include <cuda_runtime.h>
#include <cuda_bf16.h>
#include <cstdint>

#define Bsz 2
#define S   2048
#define D   1024
#define H   16
#define HD  64
#define EPSV 1e-8f

// ---------------- scratch (__device__ globals; alloc-free rule) -------------
__device__ __nv_bfloat16 g_xh[(size_t)Bsz * S * D];
__device__ __nv_bfloat16 g_xl[(size_t)Bsz * S * D];
__device__ __nv_bfloat16 g_w1h[(size_t)2 * D * D];
__device__ __nv_bfloat16 g_w1l[(size_t)2 * D * D];
__device__ __nv_bfloat16 g_w3h[(size_t)D * D];
__device__ __nv_bfloat16 g_w3l[(size_t)D * D];
__device__ __nv_bfloat16 g_qkh[(size_t)Bsz * S * 2 * D];  // stage1 out hi: [4096][2048] Q|K
__device__ __nv_bfloat16 g_qkl[(size_t)Bsz * S * 2 * D];  // stage1 out lo
__device__ __nv_bfloat16 g_vbh[(size_t)Bsz * S * D];      // V bf16 hi
__device__ __nv_bfloat16 g_vbl[(size_t)Bsz * S * D];      // V bf16 lo
__device__ __nv_bfloat16 g_ath[(size_t)Bsz * S * D];      // attention out hi
__device__ __nv_bfloat16 g_atl[(size_t)Bsz * S * D];      // attention out lo

// ---------------- helpers (all plain sm_80+ PTX; no 'a' features) -----------
__device__ __forceinline__ uint32_t smem_u32(const void* p) {
    uint32_t a;
    asm("{ .reg .u64 t; cvta.to.shared.u64 t, %1; cvt.u32.u64 %0, t; }" : "=r"(a) : "l"(p));
    return a;
}
__device__ __forceinline__ void cp16(uint32_t dst, const void* src) {
    asm volatile("cp.async.cg.shared.global [%0], [%1], 16;" :: "r"(dst), "l"(src));
}
__device__ __forceinline__ void cp_commit() {
    asm volatile("cp.async.commit_group;" ::: "memory");
}
__device__ __forceinline__ void cp_wait0() {
    asm volatile("cp.async.wait_group 0;" ::: "memory");
}
__device__ __forceinline__ void cp_wait1() {
    asm volatile("cp.async.wait_group 1;" ::: "memory");
}
__device__ __forceinline__ void ldsm_x4(uint32_t (&r)[4], uint32_t addr) {
    asm volatile("ldmatrix.sync.aligned.m8n8.x4.shared.b16 {%0,%1,%2,%3}, [%4];"
                 : "=r"(r[0]), "=r"(r[1]), "=r"(r[2]), "=r"(r[3]) : "r"(addr));
}
__device__ __forceinline__ void ldsm_x4_t(uint32_t (&r)[4], uint32_t addr) {
    asm volatile("ldmatrix.sync.aligned.m8n8.x4.trans.shared.b16 {%0,%1,%2,%3}, [%4];"
                 : "=r"(r[0]), "=r"(r[1]), "=r"(r[2]), "=r"(r[3]) : "r"(addr));
}
__device__ __forceinline__ void mma16816(float (&c)[4], const uint32_t (&a)[4],
                                         uint32_t b0, uint32_t b1) {
    asm volatile(
        "mma.sync.aligned.m16n8k16.row.col.f32.bf16.bf16.f32 "
        "{%0,%1,%2,%3}, {%4,%5,%6,%7}, {%8,%9}, {%0,%1,%2,%3};"
        : "+f"(c[0]), "+f"(c[1]), "+f"(c[2]), "+f"(c[3])
        : "r"(a[0]), "r"(a[1]), "r"(a[2]), "r"(a[3]), "r"(b0), "r"(b1));
}
__device__ __forceinline__ uint32_t bf2pack(float lo, float hi) {
    uint32_t r;
    asm("cvt.rn.bf16x2.f32 %0, %1, %2;" : "=r"(r) : "f"(hi), "f"(lo));
    return r;
}
__device__ __forceinline__ void split_store(__nv_bfloat16* Oh, __nv_bfloat16* Ol,
                                            size_t idx, float v0, float v1) {
    __nv_bfloat16 h0 = __float2bfloat16(v0), h1 = __float2bfloat16(v1);
    __nv_bfloat162 hp; hp.x = h0; hp.y = h1;
    __nv_bfloat162 lp;
    lp.x = __float2bfloat16(v0 - __bfloat162float(h0));
    lp.y = __float2bfloat16(v1 - __bfloat162float(h1));
    *(__nv_bfloat162*)(Oh + idx) = hp;
    *(__nv_bfloat162*)(Ol + idx) = lp;
}

// ---------------------------------------------------------------------------
// conversions
// ---------------------------------------------------------------------------
__global__ __launch_bounds__(256)
void conv_split(const float* __restrict__ in, __nv_bfloat16* __restrict__ hi,
                __nv_bfloat16* __restrict__ lo, int n4) {
    int i = blockIdx.x * 256 + threadIdx.x;
    if (i >= n4) return;
    float4 v = *(const float4*)(in + (size_t)i * 4);
    split_store(hi, lo, (size_t)i * 4, v.x, v.y);
    split_store(hi, lo, (size_t)i * 4 + 2, v.z, v.w);
}

// ---------------------------------------------------------------------------
// mma.sync bf16x3 GEMM: C = (Ah+Al)[M][K] * (Bh+Bl)[N][K]^T + bias
// 128x128 tile, BK=32, cp.async double-buffered. 8 warps (2x4), each 64x32.
// mode 0: fp32 out to Cf. mode 1: bf16 hi/lo split out to Oh/Ol.
// ---------------------------------------------------------------------------
#define GEMM_SMEM (2 * 20480 * 2)   // 2 buffers x 20480 halves

__device__ __forceinline__ void gemm_issue(
    const __nv_bfloat16* Ah, const __nv_bfloat16* Al,
    const __nv_bfloat16* Bh, const __nv_bfloat16* Bl,
    int K, int row0, int col0, int chunk, uint32_t dstbase, int tid) {
    #pragma unroll
    for (int j = 0; j < 8; j++) {
        int linear = tid + j * 256;
        int arr = linear >> 9, rem = linear & 511;
        int r = rem >> 2, c = rem & 3;
        const __nv_bfloat16* src = (arr == 0) ? Ah : (arr == 1) ? Al : (arr == 2) ? Bh : Bl;
        int grow = ((arr < 2) ? row0 : col0) + r;
        cp16(dstbase + (uint32_t)(arr * 5120 + r * 40 + c * 8) * 2,
             src + (size_t)grow * K + chunk * 32 + c * 8);
    }
}

__global__ __launch_bounds__(256, 2)
void mma_gemm(const __nv_bfloat16* __restrict__ Ah, const __nv_bfloat16* __restrict__ Al,
              const __nv_bfloat16* __restrict__ Bh, const __nv_bfloat16* __restrict__ Bl,
              const float* __restrict__ bias, float* __restrict__ Cf,
              __nv_bfloat16* __restrict__ Oh, __nv_bfloat16* __restrict__ Ol,
              int K, int N, int mode) {
    extern __shared__ __nv_bfloat16 smem[];
    const int tid = threadIdx.x;
    const int wid = tid >> 5, lane = tid & 31;
    const int wr = wid >> 2, wc = wid & 3;
    const int row0 = blockIdx.y * 128, col0 = blockIdx.x * 128;
    const uint32_t sb = smem_u32(smem);

    float acc[4][4][4] = {};

    gemm_issue(Ah, Al, Bh, Bl, K, row0, col0, 0, sb, tid);
    cp_commit();

    const int nch = K / 32;
    for (int ch = 0; ch < nch; ++ch) {
        const int p = ch & 1;
        if (ch + 1 < nch) {
            gemm_issue(Ah, Al, Bh, Bl, K, row0, col0, ch + 1, sb + (p ^ 1) * 40960, tid);
            cp_commit();
            cp_wait1();
        } else {
            cp_wait0();
        }
        __syncthreads();

        const uint32_t bufb = sb + p * 40960;
        #pragma unroll
        for (int t = 0; t < 3; t++) {
            const uint32_t aoff = (t == 2) ? 5120u : 0u;
            const uint32_t boff = (t == 1) ? 15360u : 10240u;
            #pragma unroll
            for (int kk = 0; kk < 2; kk++) {
                uint32_t a[4][4];
                #pragma unroll
                for (int i = 0; i < 4; i++)
                    ldsm_x4(a[i], bufb + (aoff + (uint32_t)((wr * 64 + i * 16 + (lane & 15)) * 40
                                                  + kk * 16 + (lane >> 4) * 8)) * 2);
                #pragma unroll
                for (int jp = 0; jp < 2; jp++) {
                    uint32_t r4[4];
                    ldsm_x4(r4, bufb + (boff + (uint32_t)((wc * 32 + jp * 16 + (lane & 15)) * 40
                                                  + kk * 16 + (lane >> 4) * 8)) * 2);
                    #pragma unroll
                    for (int i = 0; i < 4; i++) {
                        mma16816(acc[i][jp * 2 + 0], a[i], r4[0], r4[2]);
                        mma16816(acc[i][jp * 2 + 1], a[i], r4[1], r4[3]);
                    }
                }
            }
        }
        __syncthreads();
    }

    // epilogue
    #pragma unroll
    for (int j = 0; j < 4; j++) {
        const int col = col0 + wc * 32 + j * 8 + (lane & 3) * 2;
        const float b0 = bias[col], b1 = bias[col + 1];
        #pragma unroll
        for (int i = 0; i < 4; i++) {
            const int row = row0 + wr * 64 + i * 16 + (lane >> 2);
            float v0 = acc[i][j][0] + b0, v1 = acc[i][j][1] + b1;
            float w0 = acc[i][j][2] + b0, w1 = acc[i][j][3] + b1;
            if (mode == 0) {
                *(float2*)(Cf + (size_t)row * N + col) = make_float2(v0, v1);
                *(float2*)(Cf + (size_t)(row + 8) * N + col) = make_float2(w0, w1);
            } else {
                split_store(Oh, Ol, (size_t)row * N + col, v0, v1);
                split_store(Oh, Ol, (size_t)(row + 8) * N + col, w0, w1);
            }
        }
    }
}

// ---------------------------------------------------------------------------
// Attention via mma.sync. Per CTA: 128 q rows, (b,h) from grid; 8 warps x 16q.
// Scores = 3-term bf16 split (QhKh + QhKl + QlKh); exp/mask in regs;
// P split hi/lo in regs; PV = 3-term split (PhVh + PhVl + PlVh).
// Single pass: Z, Zm, O accumulate; out = O / (Zm + EPS*Z).
// ---------------------------------------------------------------------------
// smem halves: Qh@0 (128*72), Ql@9216, buffers @18432
//   per buf 18432: Kh@0, Kl@4608, Vh@9216, Vl@13824
#define ATTN_SMEM ((18432 + 2 * 18432) * 2)

__device__ __forceinline__ void attn_issue_kv(int b, int h, int it, uint32_t sb,
                                              int p, int tid) {
    const int k0 = it * 64;
    #pragma unroll
    for (int j = 0; j < 8; j++) {
        int linear = tid + j * 256;
        int arr = linear >> 9, rem = linear & 511;
        int r = rem >> 3, c = rem & 7;
        const __nv_bfloat16* src;
        if (arr == 0)      src = g_qkh + (size_t)(b * S + k0 + r) * 2048 + D + h * 64 + c * 8;
        else if (arr == 1) src = g_qkl + (size_t)(b * S + k0 + r) * 2048 + D + h * 64 + c * 8;
        else if (arr == 2) src = g_vbh + (size_t)(b * S + k0 + r) * 1024 + h * 64 + c * 8;
        else               src = g_vbl + (size_t)(b * S + k0 + r) * 1024 + h * 64 + c * 8;
        cp16(sb + (uint32_t)(18432 + p * 18432 + arr * 4608 + r * 72 + c * 8) * 2, src);
    }
}

__global__ __launch_bounds__(256)
void attn_mma(const float* __restrict__ Min) {
    extern __shared__ __nv_bfloat16 smem[];
    const int tid = threadIdx.x;
    const int wid = tid >> 5, lane = tid & 31;
    const int b = blockIdx.z, h = blockIdx.y;
    const int q0 = blockIdx.x * 128;
    const uint32_t sb = smem_u32(smem);

    // Q hi/lo -> smem (group 0 together with iter-0 K/V)
    #pragma unroll
    for (int j = 0; j < 8; j++) {
        int linear = tid + j * 256;
        int arr = linear >> 10, rem = linear & 1023;
        int r = rem >> 3, c = rem & 7;
        const __nv_bfloat16* src = (arr ? g_qkl : g_qkh)
            + (size_t)(b * S + q0 + r) * 2048 + h * 64 + c * 8;
        cp16(sb + (uint32_t)(arr * 9216 + r * 72 + c * 8) * 2, src);
    }
    attn_issue_kv(b, h, 0, sb, 0, tid);
    cp_commit();

    float Oc[8][4] = {};
    float z0 = 0.f, z1 = 0.f, zm0 = 0.f, zm1 = 0.f;

    const int niter = S / 64;
    for (int it = 0; it < niter; ++it) {
        const int p = it & 1;
        if (it + 1 < niter) {
            attn_issue_kv(b, h, it + 1, sb, p ^ 1, tid);
            cp_commit();
            cp_wait1();
        } else {
            cp_wait0();
        }
        __syncthreads();

        // mask prefetch into regs (overlaps with score MMAs)
        const float* mb = Min + ((size_t)(b * S + q0 + wid * 16 + (lane >> 2))) * S
                          + it * 64 + (lane & 3) * 2;
        float2 m0[8], m1[8];
        #pragma unroll
        for (int j = 0; j < 8; j++) {
            m0[j] = *(const float2*)(mb + j * 8);
            m1[j] = *(const float2*)(mb + (size_t)8 * S + j * 8);
        }

        // scores: 3-term split
        float sc[8][4] = {};
        #pragma unroll
        for (int t = 0; t < 3; t++) {
            const uint32_t qoff = (t == 2) ? 9216u : 0u;
            const uint32_t koff = 18432u + (uint32_t)p * 18432u + ((t == 1) ? 4608u : 0u);
            #pragma unroll
            for (int kk = 0; kk < 4; kk++) {
                uint32_t a[4];
                ldsm_x4(a, sb + (qoff + (uint32_t)((wid * 16 + (lane & 15)) * 72
                                      + kk * 16 + (lane >> 4) * 8)) * 2);
                #pragma unroll
                for (int jp = 0; jp < 4; jp++) {
                    uint32_t r4[4];
                    ldsm_x4(r4, sb + (koff + (uint32_t)((jp * 16 + (lane & 15)) * 72
                                          + kk * 16 + (lane >> 4) * 8)) * 2);
                    mma16816(sc[jp * 2 + 0], a, r4[0], r4[2]);
                    mma16816(sc[jp * 2 + 1], a, r4[1], r4[3]);
                }
            }
        }

        // exp + mask + sums + repack P (split hi/lo) into a-frags
        uint32_t pah[4][4], pal[4][4];
        #pragma unroll
        for (int j = 0; j < 8; j++) {
            float e0 = __expf(sc[j][0] * 0.125f);
            float e1 = __expf(sc[j][1] * 0.125f);
            float e2 = __expf(sc[j][2] * 0.125f);
            float e3 = __expf(sc[j][3] * 0.125f);
            z0 += e0 + e1; z1 += e2 + e3;
            float em0 = e0 * m0[j].x, em1 = e1 * m0[j].y;
            float em2 = e2 * m1[j].x, em3 = e3 * m1[j].y;
            zm0 += em0 + em1; zm1 += em2 + em3;
            float h0 = __bfloat162float(__float2bfloat16(em0));
            float h1 = __bfloat162float(__float2bfloat16(em1));
            float h2 = __bfloat162float(__float2bfloat16(em2));
            float h3 = __bfloat162float(__float2bfloat16(em3));
            pah[j >> 1][(j & 1) * 2 + 0] = bf2pack(em0, em1);
            pah[j >> 1][(j & 1) * 2 + 1] = bf2pack(em2, em3);
            pal[j >> 1][(j & 1) * 2 + 0] = bf2pack(em0 - h0, em1 - h1);
            pal[j >> 1][(j & 1) * 2 + 1] = bf2pack(em2 - h2, em3 - h3);
        }

        // PV: 3-term split (PhVh + PhVl + PlVh)
        #pragma unroll
        for (int t = 0; t < 3; t++) {
            const uint32_t voff = 18432u + (uint32_t)p * 18432u
                                + ((t == 1) ? 13824u : 9216u);
            #pragma unroll
            for (int j2 = 0; j2 < 4; j2++) {
                const int krow = j2 * 16 + ((lane >> 3) & 1) * 8 + (lane & 7);
                #pragma unroll
                for (int ndp = 0; ndp < 4; ndp++) {
                    uint32_t r4[4];
                    ldsm_x4_t(r4, sb + (voff + (uint32_t)(krow * 72
                                            + ndp * 16 + (lane >> 4) * 8)) * 2);
                    if (t == 2) {
                        mma16816(Oc[ndp * 2 + 0], pal[j2], r4[0], r4[1]);
                        mma16816(Oc[ndp * 2 + 1], pal[j2], r4[2], r4[3]);
                    } else {
                        mma16816(Oc[ndp * 2 + 0], pah[j2], r4[0], r4[1]);
                        mma16816(Oc[ndp * 2 + 1], pah[j2], r4[2], r4[3]);
                    }
                }
            }
        }
        __syncthreads();
    }

    // quad reduce (lanes sharing lane>>2 hold the same rows)
    #pragma unroll
    for (int off = 1; off < 4; off <<= 1) {
        z0  += __shfl_xor_sync(0xffffffffu, z0, off);
        z1  += __shfl_xor_sync(0xffffffffu, z1, off);
        zm0 += __shfl_xor_sync(0xffffffffu, zm0, off);
        zm1 += __shfl_xor_sync(0xffffffffu, zm1, off);
    }
    const float inv0 = 1.0f / (zm0 + EPSV * z0);
    const float inv1 = 1.0f / (zm1 + EPSV * z1);

    const int row = b * S + q0 + wid * 16 + (lane >> 2);
    #pragma unroll
    for (int nd = 0; nd < 8; nd++) {
        const int col = h * 64 + nd * 8 + (lane & 3) * 2;
        split_store(g_ath, g_atl, (size_t)row * D + col,
                    Oc[nd][0] * inv0, Oc[nd][1] * inv0);
        split_store(g_ath, g_atl, (size_t)(row + 8) * D + col,
                    Oc[nd][2] * inv1, Oc[nd][3] * inv1);
    }
}

// ---------------------------------------------------------------------------
extern "C" void kernel_launch(void* const* d_in, const int* in_sizes, int n_in,
                              void* d_out, int out_size) {
    const float* x         = (const float*)d_in[0];  // [B,S,D]
    const float* Vin       = (const float*)d_in[1];  // [B,S,H,HD]
    const float* Min       = (const float*)d_in[2];  // [B,S,S]
    const float* in_proj_w = (const float*)d_in[3];  // [3D,D]
    const float* in_proj_b = (const float*)d_in[4];  // [3D]
    const float* out_w     = (const float*)d_in[5];  // [D,D]
    const float* out_b     = (const float*)d_in[6];  // [D]
    float* out             = (float*)d_out;          // [B,S,D]

    __nv_bfloat16 *xh, *xl, *w1h, *w1l, *w3h, *w3l, *qkh, *qkl, *vbh, *vbl, *ath, *atl;
    cudaGetSymbolAddress((void**)&xh,  g_xh);
    cudaGetSymbolAddress((void**)&xl,  g_xl);
    cudaGetSymbolAddress((void**)&w1h, g_w1h);
    cudaGetSymbolAddress((void**)&w1l, g_w1l);
    cudaGetSymbolAddress((void**)&w3h, g_w3h);
    cudaGetSymbolAddress((void**)&w3l, g_w3l);
    cudaGetSymbolAddress((void**)&qkh, g_qkh);
    cudaGetSymbolAddress((void**)&qkl, g_qkl);
    cudaGetSymbolAddress((void**)&vbh, g_vbh);
    cudaGetSymbolAddress((void**)&vbl, g_vbl);
    cudaGetSymbolAddress((void**)&ath, g_ath);
    cudaGetSymbolAddress((void**)&atl, g_atl);

    cudaFuncSetAttribute(mma_gemm, cudaFuncAttributeMaxDynamicSharedMemorySize, GEMM_SMEM);
    cudaFuncSetAttribute(attn_mma, cudaFuncAttributeMaxDynamicSharedMemorySize, ATTN_SMEM);

    const int Mtot = Bsz * S;  // 4096

    // conversions (bf16 hi/lo splits)
    conv_split<<<(Mtot * D / 4 + 255) / 256, 256>>>(x, xh, xl, Mtot * D / 4);
    conv_split<<<(2 * D * D / 4 + 255) / 256, 256>>>(in_proj_w, w1h, w1l, 2 * D * D / 4);
    conv_split<<<(D * D / 4 + 255) / 256, 256>>>(out_w, w3h, w3l, D * D / 4);
    conv_split<<<(Mtot * D / 4 + 255) / 256, 256>>>(Vin, vbh, vbl, Mtot * D / 4);

    // Stage 1: [Q|K] = x @ in_proj_w[0:2D]^T + b  -> bf16 hi/lo [4096][2048]
    mma_gemm<<<dim3((2 * D) / 128, Mtot / 128), 256, GEMM_SMEM>>>(
        xh, xl, w1h, w1l, in_proj_b, nullptr, qkh, qkl, D, 2 * D, 1);

    // Stage 2: masked-renormalized attention -> bf16 hi/lo [4096][1024]
    attn_mma<<<dim3(S / 128, H, Bsz), 256, ATTN_SMEM>>>(Min);

    // Stage 3: out = attn @ out_w^T + out_b  (fp32)
    mma_gemm<<<dim3(D / 128, Mtot / 128), 256, GEMM_SMEM>>>(
        ath, atl, w3h, w3l, out_b, out, nullptr, nullptr, D, D, 0);
}